// round 5
// baseline (speedup 1.0000x reference)
#include <cuda_runtime.h>
#include <cstdint>

#define NFIELDS 32
#define EMBED   64
#define NPAIRS  496
#define BATCH   2048
#define EMB_ROW (NFIELDS * EMBED)   // 2048 floats per batch
#define KER_ROW (NPAIRS * EMBED)    // 31744 floats per i row

#define BM      128                 // batches per block (M tile)
#define PCHUNK  8                   // pairs per block (all share one r)
#define NCHUNKS 76                  // sum over r of ceil((31-r)/8)
#define NTHREADS 256

__device__ __forceinline__ uint32_t f2tf32(float x) {
    uint32_t r;
    asm("cvt.rna.tf32.f32 %0, %1;" : "=r"(r) : "f"(x));
    return r;
}

__device__ __forceinline__ void mma_tf32(float* d, uint32_t a0, uint32_t a1,
                                         uint32_t a2, uint32_t a3,
                                         uint32_t b0, uint32_t b1) {
    asm("mma.sync.aligned.m16n8k8.row.col.f32.tf32.tf32.f32 "
        "{%0,%1,%2,%3}, {%4,%5,%6,%7}, {%8,%9}, {%0,%1,%2,%3};"
        : "+f"(d[0]), "+f"(d[1]), "+f"(d[2]), "+f"(d[3])
        : "r"(a0), "r"(a1), "r"(a2), "r"(a3), "r"(b0), "r"(b1));
}

// sB[(kt*8+nt)*32 + lane] = {Kp[n][k], Kp[n][k+4]}, n = nt*8+lane/4, k = kt*8+lane%4
__device__ __forceinline__ void stage_B(uint2* __restrict__ sB,
                                        const float* __restrict__ Kb, int t) {
    #pragma unroll
    for (int it = 0; it < 8; ++it) {
        int idx = it * NTHREADS + t;       // 0..2047
        int l   = idx & 31;
        int nt  = (idx >> 5) & 7;
        int kt  = idx >> 8;
        const float* src = Kb + (size_t)(nt * 8 + (l >> 2)) * KER_ROW + kt * 8 + (l & 3);
        uint2 f;
        f.x = f2tf32(src[0]);
        f.y = f2tf32(src[4]);
        sB[idx] = f;
    }
}

__global__ void __launch_bounds__(NTHREADS, 2)
opn_mma_kernel(const float* __restrict__ emb, const float* __restrict__ ker,
               float* __restrict__ out)
{
    // smem: sA 2048*uint4 (32KB) | sB0/sB1 2048*uint2 (16KB each) | sRed 2*128 f32
    extern __shared__ __align__(16) uint4 dynsmem[];
    uint4* sAfrag = dynsmem;
    uint2* sB0 = (uint2*)(dynsmem + 2048);
    uint2* sB1 = sB0 + 2048;
    float* sRed = (float*)(sB1 + 2048);

    const int t    = threadIdx.x;
    const int w    = t >> 5;
    const int lane = t & 31;
    const int wm   = w & 3;     // M group: rows [wm*32, wm*32+32)
    const int wn   = w >> 2;    // N group: cols [wn*32, wn*32+32)
    const int batch_base = blockIdx.x * BM;

    // ---- decode chunk id -> (r, first pair p0, #pairs np, first col c0) ----
    int cid = blockIdx.y, r = 0, pbase = 0;
    while (true) {
        int cnt = 31 - r;
        int nch = (cnt + PCHUNK - 1) >> 3;
        if (cid < nch) break;
        cid -= nch; pbase += cnt; ++r;
    }
    const int p0 = pbase + cid * PCHUNK;
    const int np = min(PCHUNK, (31 - r) - cid * PCHUNK);
    const int c0 = r + 1 + cid * PCHUNK;

    // ---- stage A fragments for P = emb[:, r, :] (once per block) ----
    // sAfrag[(kt*8+mt)*32+lane] = {P[m][k], P[m+8][k], P[m][k+4], P[m+8][k+4]},
    // m = mt*16 + lane/4, k = kt*8 + lane%4
    {
        const float* Pb = emb + (size_t)batch_base * EMB_ROW + (size_t)r * EMBED;
        #pragma unroll
        for (int it = 0; it < 8; ++it) {
            int idx = it * NTHREADS + t;
            int l   = idx & 31;
            int mt  = (idx >> 5) & 7;
            int kt  = idx >> 8;
            const float* row0 = Pb + (size_t)(mt * 16 + (l >> 2)) * EMB_ROW + kt * 8 + (l & 3);
            const float* row1 = row0 + 8 * EMB_ROW;
            uint4 f;
            f.x = f2tf32(row0[0]);
            f.y = f2tf32(row1[0]);
            f.z = f2tf32(row0[4]);
            f.w = f2tf32(row1[4]);
            sAfrag[idx] = f;
        }
    }
    stage_B(sB0, ker + (size_t)p0 * EMBED, t);
    __syncthreads();

    // ---- pair loop ----
    for (int k = 0; k < np; ++k) {
        uint2* sBc = (k & 1) ? sB1 : sB0;
        uint2* sBn = (k & 1) ? sB0 : sB1;
        float* sRedBuf = sRed + (k & 1) * BM;

        if (k + 1 < np)
            stage_B(sBn, ker + (size_t)(p0 + k + 1) * EMBED, t);

        float acc[2][4][4];
        #pragma unroll
        for (int mm = 0; mm < 2; ++mm)
            #pragma unroll
            for (int nn = 0; nn < 4; ++nn)
                #pragma unroll
                for (int u = 0; u < 4; ++u)
                    acc[mm][nn][u] = 0.f;

        #pragma unroll
        for (int kt = 0; kt < 8; ++kt) {
            uint4 A[2];
            #pragma unroll
            for (int mm = 0; mm < 2; ++mm)
                A[mm] = sAfrag[(kt * 8 + (wm * 2 + mm)) * 32 + lane];
            uint2 B[4];
            #pragma unroll
            for (int nn = 0; nn < 4; ++nn)
                B[nn] = sBc[(kt * 8 + (wn * 4 + nn)) * 32 + lane];

            #pragma unroll
            for (int mm = 0; mm < 2; ++mm)
                #pragma unroll
                for (int nn = 0; nn < 4; ++nn)
                    mma_tf32(acc[mm][nn], A[mm].x, A[mm].y, A[mm].z, A[mm].w,
                             B[nn].x, B[nn].y);
        }

        // ---- epilogue: dot with q = emb[b, c, :] over this warp's 32 cols ----
        const int c = c0 + k;
        const int p = p0 + k;
        float sv0[2], sv1[2];
        #pragma unroll
        for (int mm = 0; mm < 2; ++mm) {
            const int row0 = (wm * 2 + mm) * 16 + (lane >> 2);
            const float* q0 = emb + (size_t)(batch_base + row0) * EMB_ROW + (size_t)c * EMBED;
            const float* q1 = q0 + 8 * EMB_ROW;

            float s0 = 0.f, s1 = 0.f;
            #pragma unroll
            for (int nn = 0; nn < 4; ++nn) {
                const int col0 = (wn * 4 + nn) * 8 + (lane & 3) * 2;
                float2 qv0 = *(const float2*)(q0 + col0);
                float2 qv1 = *(const float2*)(q1 + col0);
                s0 += acc[mm][nn][0] * qv0.x + acc[mm][nn][1] * qv0.y;
                s1 += acc[mm][nn][2] * qv1.x + acc[mm][nn][3] * qv1.y;
            }
            s0 += __shfl_xor_sync(0xffffffffu, s0, 1);
            s0 += __shfl_xor_sync(0xffffffffu, s0, 2);
            s1 += __shfl_xor_sync(0xffffffffu, s1, 1);
            s1 += __shfl_xor_sync(0xffffffffu, s1, 2);
            sv0[mm] = s0;
            sv1[mm] = s1;
        }

        // wn=1 warps publish partials; single sync; wn=0 combines + stores
        if (wn == 1 && (lane & 3) == 0) {
            #pragma unroll
            for (int mm = 0; mm < 2; ++mm) {
                const int row = (wm * 2 + mm) * 16 + (lane >> 2);
                sRedBuf[row]     = sv0[mm];
                sRedBuf[row + 8] = sv1[mm];
            }
        }
        __syncthreads();   // covers sRedBuf AND sBn for the next iteration
        if (wn == 0 && (lane & 3) == 0) {
            #pragma unroll
            for (int mm = 0; mm < 2; ++mm) {
                const int row = (wm * 2 + mm) * 16 + (lane >> 2);
                out[(size_t)(batch_base + row)     * NPAIRS + p] = sv0[mm] + sRedBuf[row];
                out[(size_t)(batch_base + row + 8) * NPAIRS + p] = sv1[mm] + sRedBuf[row + 8];
            }
        }
    }
}

#define SMEM_TOTAL (2048 * 16 + 2 * 2048 * 8 + 2 * BM * 4)   // 65.5 KB

extern "C" void kernel_launch(void* const* d_in, const int* in_sizes, int n_in,
                              void* d_out, int out_size) {
    const float* emb = (const float*)d_in[0];   // (2048, 32, 64) f32
    const float* ker = (const float*)d_in[1];   // (64, 496, 64) f32
    float* out = (float*)d_out;                 // (2048, 1, 496) f32
    (void)in_sizes; (void)n_in; (void)out_size;

    static bool attr_set = false;
    if (!attr_set) {
        cudaFuncSetAttribute(opn_mma_kernel,
                             cudaFuncAttributeMaxDynamicSharedMemorySize, SMEM_TOTAL);
        attr_set = true;
    }
    dim3 grid(BATCH / BM, NCHUNKS);
    opn_mma_kernel<<<grid, NTHREADS, SMEM_TOTAL>>>(emb, ker, out);
}

// round 6
// speedup vs baseline: 1.0669x; 1.0669x over previous
#include <cuda_runtime.h>
#include <cstdint>

#define NFIELDS 32
#define EMBED   64
#define NPAIRS  496
#define BATCH   2048
#define EMB_ROW (NFIELDS * EMBED)   // 2048 floats per batch
#define KER_ROW (NPAIRS * EMBED)    // 31744 floats per i row

#define BM      128                 // batches per block
#define PCHUNK  8                   // pairs per block (all share one r)
#define NCHUNKS 76                  // sum over r of ceil((31-r)/8)
#define NTHREADS 256

__device__ __forceinline__ uint32_t f2tf32(float x) {
    uint32_t r;
    asm("cvt.rna.tf32.f32 %0, %1;" : "=r"(r) : "f"(x));
    return r;
}

__device__ __forceinline__ void mma_tf32(float* d, uint32_t a0, uint32_t a1,
                                         uint32_t a2, uint32_t a3,
                                         uint32_t b0, uint32_t b1) {
    asm("mma.sync.aligned.m16n8k8.row.col.f32.tf32.tf32.f32 "
        "{%0,%1,%2,%3}, {%4,%5,%6,%7}, {%8,%9}, {%0,%1,%2,%3};"
        : "+f"(d[0]), "+f"(d[1]), "+f"(d[2]), "+f"(d[3])
        : "r"(a0), "r"(a1), "r"(a2), "r"(a3), "r"(b0), "r"(b1));
}

// B fragments, two nt packed per uint4:
// sB[(kt*4+h)*32 + lane] = {K[n0][k], K[n0][k+4], K[n0+8][k], K[n0+8][k+4]},
// n0 = h*16 + lane/4, k = kt*8 + lane%4  (covers nt = 2h and 2h+1)
__device__ __forceinline__ void stage_B4(uint4* __restrict__ sB,
                                         const float* __restrict__ Kb, int t) {
    #pragma unroll
    for (int it = 0; it < 4; ++it) {
        int idx = it * NTHREADS + t;       // 0..1023
        int l   = idx & 31;
        int h   = (idx >> 5) & 3;
        int kt  = idx >> 7;
        const float* s0 = Kb + (size_t)(h * 16 + (l >> 2)) * KER_ROW + kt * 8 + (l & 3);
        const float* s1 = s0 + 8 * KER_ROW;
        uint4 f;
        f.x = f2tf32(s0[0]);
        f.y = f2tf32(s0[4]);
        f.z = f2tf32(s1[0]);
        f.w = f2tf32(s1[4]);
        sB[idx] = f;
    }
}

__global__ void __launch_bounds__(NTHREADS, 2)
opn_mma_kernel(const float* __restrict__ emb, const float* __restrict__ ker,
               float* __restrict__ out)
{
    // smem: sA 2048*uint4 (32KB) | sB 4 buffers x 1024*uint4 (16KB each) | sOut 128*8 f32
    extern __shared__ __align__(16) uint4 dynsmem[];
    uint4* sA   = dynsmem;                    // A fragments
    uint4* sB   = dynsmem + 2048;             // 4 * 1024 uint4
    float* sOut = (float*)(sB + 4 * 1024);    // [row][8]

    const int t    = threadIdx.x;
    const int w    = t >> 5;
    const int lane = t & 31;
    const int wp   = w & 1;     // pair within group
    const int ws   = w >> 1;    // batch strip: rows [ws*32, ws*32+32)
    const int batch_base = blockIdx.x * BM;

    // ---- decode chunk id -> (r, first pair p0, #pairs np, first col c0) ----
    int cid = blockIdx.y, r = 0, pbase = 0;
    while (true) {
        int cnt = 31 - r;
        int nch = (cnt + PCHUNK - 1) >> 3;
        if (cid < nch) break;
        cid -= nch; pbase += cnt; ++r;
    }
    const int p0 = pbase + cid * PCHUNK;
    const int np = min(PCHUNK, (31 - r) - cid * PCHUNK);
    const int c0 = r + 1 + cid * PCHUNK;

    // ---- stage A fragments for P = emb[:, r, :] (once per block) ----
    // sA[(kt*8+mt)*32+lane] = {P[m][k], P[m+8][k], P[m][k+4], P[m+8][k+4]},
    // m = mt*16 + lane/4, k = kt*8 + lane%4
    {
        const float* Pb = emb + (size_t)batch_base * EMB_ROW + (size_t)r * EMBED;
        #pragma unroll
        for (int it = 0; it < 8; ++it) {
            int idx = it * NTHREADS + t;
            int l   = idx & 31;
            int mt  = (idx >> 5) & 7;
            int kt  = idx >> 8;
            const float* row0 = Pb + (size_t)(mt * 16 + (l >> 2)) * EMB_ROW + kt * 8 + (l & 3);
            const float* row1 = row0 + 8 * EMB_ROW;
            uint4 f;
            f.x = f2tf32(row0[0]);
            f.y = f2tf32(row1[0]);
            f.z = f2tf32(row0[4]);
            f.w = f2tf32(row1[4]);
            sA[idx] = f;
        }
    }
    // ---- stage B for first group (pairs p0, p0+1) ----
    stage_B4(sB, ker + (size_t)p0 * EMBED, t);
    if (np > 1) stage_B4(sB + 1024, ker + (size_t)(p0 + 1) * EMBED, t);
    __syncthreads();

    // ---- group loop: 2 pairs per group, each warp owns (pair, 32-row strip) ----
    const int ng = (np + 1) >> 1;
    for (int g = 0; g < ng; ++g) {
        const int cur = (g & 1) * 2;
        const int nxt = cur ^ 2;

        // prefetch next group's B (overlaps with MMA + epilogue)
        if (g + 1 < ng) {
            int pi = 2 * (g + 1);
            stage_B4(sB + nxt * 1024, ker + (size_t)(p0 + pi) * EMBED, t);
            if (pi + 1 < np)
                stage_B4(sB + (nxt + 1) * 1024, ker + (size_t)(p0 + pi + 1) * EMBED, t);
        }

        const int j = 2 * g + wp;          // pair slot within chunk
        if (j < np) {
            const uint4* sBc = sB + (cur + wp) * 1024;

            float acc[2][8][4];
            #pragma unroll
            for (int mm = 0; mm < 2; ++mm)
                #pragma unroll
                for (int nt = 0; nt < 8; ++nt)
                    #pragma unroll
                    for (int u = 0; u < 4; ++u)
                        acc[mm][nt][u] = 0.f;

            #pragma unroll
            for (int kt = 0; kt < 8; ++kt) {
                uint4 A[2];
                #pragma unroll
                for (int mm = 0; mm < 2; ++mm)
                    A[mm] = sA[(kt * 8 + (ws * 2 + mm)) * 32 + lane];
                uint4 B4[4];
                #pragma unroll
                for (int h = 0; h < 4; ++h)
                    B4[h] = sBc[(kt * 4 + h) * 32 + lane];

                #pragma unroll
                for (int mm = 0; mm < 2; ++mm)
                    #pragma unroll
                    for (int h = 0; h < 4; ++h) {
                        mma_tf32(acc[mm][2 * h],     A[mm].x, A[mm].y, A[mm].z, A[mm].w,
                                 B4[h].x, B4[h].y);
                        mma_tf32(acc[mm][2 * h + 1], A[mm].x, A[mm].y, A[mm].z, A[mm].w,
                                 B4[h].z, B4[h].w);
                    }
            }

            // ---- epilogue: dot with q = emb[b, c, :] (full N=64, no x-warp reduce) ----
            const int c = c0 + j;
            #pragma unroll
            for (int mm = 0; mm < 2; ++mm) {
                const int row0 = ws * 32 + mm * 16 + (lane >> 2);
                const float* q0 = emb + (size_t)(batch_base + row0) * EMB_ROW + (size_t)c * EMBED;
                const float* q1 = q0 + 8 * EMB_ROW;

                float s0 = 0.f, s1 = 0.f;
                #pragma unroll
                for (int nt = 0; nt < 8; ++nt) {
                    const int col0 = nt * 8 + (lane & 3) * 2;
                    float2 qv0 = *(const float2*)(q0 + col0);
                    float2 qv1 = *(const float2*)(q1 + col0);
                    s0 += acc[mm][nt][0] * qv0.x + acc[mm][nt][1] * qv0.y;
                    s1 += acc[mm][nt][2] * qv1.x + acc[mm][nt][3] * qv1.y;
                }
                s0 += __shfl_xor_sync(0xffffffffu, s0, 1);
                s0 += __shfl_xor_sync(0xffffffffu, s0, 2);
                s1 += __shfl_xor_sync(0xffffffffu, s1, 1);
                s1 += __shfl_xor_sync(0xffffffffu, s1, 2);

                if ((lane & 3) == 0) {
                    sOut[row0 * PCHUNK + j]       = s0;
                    sOut[(row0 + 8) * PCHUNK + j] = s1;
                }
            }
        }
        __syncthreads();   // B double-buffer + sOut ordering
    }

    // ---- coalesced output sweep: pairs are contiguous in the last dim ----
    #pragma unroll
    for (int u = 0; u < 4; ++u) {
        int idx = t * 4 + u;               // 0..1023
        int b = idx >> 3;
        int j = idx & 7;
        if (j < np)
            out[(size_t)(batch_base + b) * NPAIRS + p0 + j] = sOut[idx];
    }
}

#define SMEM_TOTAL (2048 * 16 + 4 * 1024 * 16 + BM * PCHUNK * 4)   // 100 KB

extern "C" void kernel_launch(void* const* d_in, const int* in_sizes, int n_in,
                              void* d_out, int out_size) {
    const float* emb = (const float*)d_in[0];   // (2048, 32, 64) f32
    const float* ker = (const float*)d_in[1];   // (64, 496, 64) f32
    float* out = (float*)d_out;                 // (2048, 1, 496) f32
    (void)in_sizes; (void)n_in; (void)out_size;

    static bool attr_set = false;
    if (!attr_set) {
        cudaFuncSetAttribute(opn_mma_kernel,
                             cudaFuncAttributeMaxDynamicSharedMemorySize, SMEM_TOTAL);
        attr_set = true;
    }
    dim3 grid(BATCH / BM, NCHUNKS);
    opn_mma_kernel<<<grid, NTHREADS, SMEM_TOTAL>>>(emb, ker, out);
}

// round 7
// speedup vs baseline: 1.4399x; 1.3496x over previous
#include <cuda_runtime.h>
#include <cstdint>

#define NFIELDS 32
#define EMBED   64
#define NPAIRS  496
#define BATCH   2048
#define EMB_ROW (NFIELDS * EMBED)   // 2048 floats per batch
#define KER_ROW (NPAIRS * EMBED)    // 31744 floats per i row

#define BM      128                 // batches per block
#define PCHUNK  8                   // pairs per block (all share one r)
#define NCHUNKS 76                  // sum over r of ceil((31-r)/8)
#define NTHREADS 256

#define ASTR 68                     // raw A row stride (floats): 68%32=4 -> conflict-free
#define BSTR 68                     // raw B row stride
#define A_FLOATS (BM * ASTR)        // 8704
#define B_FLOATS (EMBED * BSTR)     // 4352

__device__ __forceinline__ uint32_t f2tf32(float x) {
    uint32_t r;
    asm("cvt.rna.tf32.f32 %0, %1;" : "=r"(r) : "f"(x));
    return r;
}

__device__ __forceinline__ void mma_tf32(float* d, uint32_t a0, uint32_t a1,
                                         uint32_t a2, uint32_t a3,
                                         uint32_t b0, uint32_t b1) {
    asm("mma.sync.aligned.m16n8k8.row.col.f32.tf32.tf32.f32 "
        "{%0,%1,%2,%3}, {%4,%5,%6,%7}, {%8,%9}, {%0,%1,%2,%3};"
        : "+f"(d[0]), "+f"(d[1]), "+f"(d[2]), "+f"(d[3])
        : "r"(a0), "r"(a1), "r"(a2), "r"(a3), "r"(b0), "r"(b1));
}

// Dense stage of K_p (64 rows x 64 cols) -> raw smem [i*BSTR + j], tf32-rounded.
__device__ __forceinline__ void stage_B_raw(uint32_t* __restrict__ sB,
                                            const float* __restrict__ Kb, int t) {
    #pragma unroll
    for (int it = 0; it < 4; ++it) {
        int idx = it * NTHREADS + t;       // 0..1023 float4 slots
        int i   = idx >> 4;                // 0..63
        int j4  = idx & 15;
        float4 v = *(const float4*)(Kb + (size_t)i * KER_ROW + j4 * 4);
        uint4 w = { f2tf32(v.x), f2tf32(v.y), f2tf32(v.z), f2tf32(v.w) };
        *(uint4*)(sB + i * BSTR + j4 * 4) = w;
    }
}

__global__ void __launch_bounds__(NTHREADS, 2)
opn_mma_kernel(const float* __restrict__ emb, const float* __restrict__ ker,
               float* __restrict__ out)
{
    // smem (floats): sA raw 8704 | sB 4 x 4352 | sOut 1024
    extern __shared__ __align__(16) uint32_t dynsmem[];
    uint32_t* sA   = dynsmem;
    uint32_t* sB   = dynsmem + A_FLOATS;
    float*    sOut = (float*)(sB + 4 * B_FLOATS);

    const int t    = threadIdx.x;
    const int w    = t >> 5;
    const int lane = t & 31;
    const int wp   = w & 1;     // pair within group
    const int ws   = w >> 1;    // batch strip: rows [ws*32, ws*32+32)
    const int batch_base = blockIdx.x * BM;

    // ---- decode chunk id -> (r, first pair p0, #pairs np, first col c0) ----
    int cid = blockIdx.y, r = 0, pbase = 0;
    while (true) {
        int cnt = 31 - r;
        int nch = (cnt + PCHUNK - 1) >> 3;
        if (cid < nch) break;
        cid -= nch; pbase += cnt; ++r;
    }
    const int p0 = pbase + cid * PCHUNK;
    const int np = min(PCHUNK, (31 - r) - cid * PCHUNK);
    const int c0 = r + 1 + cid * PCHUNK;

    // ---- stage A raw: sA[b*ASTR + j] = tf32(emb[batch_base+b, r, j]) ----
    {
        const float* Pb = emb + (size_t)batch_base * EMB_ROW + (size_t)r * EMBED;
        #pragma unroll
        for (int it = 0; it < 8; ++it) {
            int idx = it * NTHREADS + t;   // 0..2047 float4 slots
            int b   = idx >> 4;            // 0..127
            int j4  = idx & 15;
            float4 v = *(const float4*)(Pb + (size_t)b * EMB_ROW + j4 * 4);
            uint4 w_ = { f2tf32(v.x), f2tf32(v.y), f2tf32(v.z), f2tf32(v.w) };
            *(uint4*)(sA + b * ASTR + j4 * 4) = w_;
        }
    }
    stage_B_raw(sB, ker + (size_t)p0 * EMBED, t);
    if (np > 1) stage_B_raw(sB + B_FLOATS, ker + (size_t)(p0 + 1) * EMBED, t);
    __syncthreads();

    // per-thread smem base offsets (in floats, uniform pattern):
    // A: row = ws*32 + mm*16 + (lane>>2) (+8), col = kt*8 + (lane&3) (+4)
    // B: row = nt*8 + (lane>>2) (+? no), col = kt*8 + (lane&3) (+4)
    const int aBase = (ws * 32 + (lane >> 2)) * ASTR + (lane & 3);
    const int bBase = (lane >> 2) * BSTR + (lane & 3);

    const int ng = (np + 1) >> 1;
    for (int g = 0; g < ng; ++g) {
        const int cur = (g & 1) * 2;
        const int nxt = cur ^ 2;

        // prefetch next group's B (dense) — overlaps with MMA + epilogue
        if (g + 1 < ng) {
            int pi = 2 * (g + 1);
            stage_B_raw(sB + nxt * B_FLOATS, ker + (size_t)(p0 + pi) * EMBED, t);
            if (pi + 1 < np)
                stage_B_raw(sB + (nxt + 1) * B_FLOATS, ker + (size_t)(p0 + pi + 1) * EMBED, t);
        }

        const int j = 2 * g + wp;          // pair slot within chunk
        if (j < np) {
            const uint32_t* Bp = sB + (cur + wp) * B_FLOATS + bBase;
            const uint32_t* Ap = sA + aBase;

            float acc[2][8][4];
            #pragma unroll
            for (int mm = 0; mm < 2; ++mm)
                #pragma unroll
                for (int nt = 0; nt < 8; ++nt)
                    #pragma unroll
                    for (int u = 0; u < 4; ++u)
                        acc[mm][nt][u] = 0.f;

            #pragma unroll
            for (int kt = 0; kt < 8; ++kt) {
                // A fragments via direct LDS.32 (conflict-free, immediate offsets)
                uint32_t a[2][4];
                #pragma unroll
                for (int mm = 0; mm < 2; ++mm) {
                    const uint32_t* Am = Ap + mm * 16 * ASTR + kt * 8;
                    a[mm][0] = Am[0];
                    a[mm][1] = Am[8 * ASTR];
                    a[mm][2] = Am[4];
                    a[mm][3] = Am[8 * ASTR + 4];
                }
                // B fragments via direct LDS.32
                uint32_t b0[8], b1[8];
                #pragma unroll
                for (int nt = 0; nt < 8; ++nt) {
                    const uint32_t* Bn = Bp + nt * 8 * BSTR + kt * 8;
                    b0[nt] = Bn[0];
                    b1[nt] = Bn[4];
                }
                #pragma unroll
                for (int mm = 0; mm < 2; ++mm)
                    #pragma unroll
                    for (int nt = 0; nt < 8; ++nt)
                        mma_tf32(acc[mm][nt], a[mm][0], a[mm][1], a[mm][2], a[mm][3],
                                 b0[nt], b1[nt]);
            }

            // ---- epilogue: dot with q = emb[b, c, :] ----
            const int c = c0 + j;
            #pragma unroll
            for (int mm = 0; mm < 2; ++mm) {
                const int row0 = ws * 32 + mm * 16 + (lane >> 2);
                const float* q0 = emb + (size_t)(batch_base + row0) * EMB_ROW + (size_t)c * EMBED;
                const float* q1 = q0 + 8 * EMB_ROW;

                float s0 = 0.f, s1 = 0.f;
                #pragma unroll
                for (int nt = 0; nt < 8; ++nt) {
                    const int col0 = nt * 8 + (lane & 3) * 2;
                    float2 qv0 = *(const float2*)(q0 + col0);
                    float2 qv1 = *(const float2*)(q1 + col0);
                    s0 += acc[mm][nt][0] * qv0.x + acc[mm][nt][1] * qv0.y;
                    s1 += acc[mm][nt][2] * qv1.x + acc[mm][nt][3] * qv1.y;
                }
                s0 += __shfl_xor_sync(0xffffffffu, s0, 1);
                s0 += __shfl_xor_sync(0xffffffffu, s0, 2);
                s1 += __shfl_xor_sync(0xffffffffu, s1, 1);
                s1 += __shfl_xor_sync(0xffffffffu, s1, 2);

                if ((lane & 3) == 0) {
                    sOut[row0 * PCHUNK + j]       = s0;
                    sOut[(row0 + 8) * PCHUNK + j] = s1;
                }
            }
        }
        __syncthreads();   // B double-buffer + sOut ordering
    }

    // ---- coalesced output sweep: pairs contiguous in last dim ----
    #pragma unroll
    for (int u = 0; u < 4; ++u) {
        int idx = t * 4 + u;               // 0..1023
        int b = idx >> 3;
        int j = idx & 7;
        if (j < np)
            out[(size_t)(batch_base + b) * NPAIRS + p0 + j] = sOut[idx];
    }
}

#define SMEM_TOTAL ((A_FLOATS + 4 * B_FLOATS + BM * PCHUNK) * 4)   // 108.5 KB

extern "C" void kernel_launch(void* const* d_in, const int* in_sizes, int n_in,
                              void* d_out, int out_size) {
    const float* emb = (const float*)d_in[0];   // (2048, 32, 64) f32
    const float* ker = (const float*)d_in[1];   // (64, 496, 64) f32
    float* out = (float*)d_out;                 // (2048, 1, 496) f32
    (void)in_sizes; (void)n_in; (void)out_size;

    static bool attr_set = false;
    if (!attr_set) {
        cudaFuncSetAttribute(opn_mma_kernel,
                             cudaFuncAttributeMaxDynamicSharedMemorySize, SMEM_TOTAL);
        attr_set = true;
    }
    dim3 grid(BATCH / BM, NCHUNKS);
    opn_mma_kernel<<<grid, NTHREADS, SMEM_TOTAL>>>(emb, ker, out);
}

// round 8
// speedup vs baseline: 1.6832x; 1.1690x over previous
#include <cuda_runtime.h>
#include <cstdint>

#define NFIELDS 32
#define EMBED   64
#define NPAIRS  496
#define BATCH   2048
#define EMB_ROW (NFIELDS * EMBED)   // 2048 floats per batch
#define KER_ROW (NPAIRS * EMBED)    // 31744 floats per i row

#define BM      128                 // batches per block
#define PCHUNK  8                   // pairs per block (all share one r)
#define NCHUNKS 76                  // sum over r of ceil((31-r)/8)
#define NTHREADS 256

#define ASTR 68                     // raw A row stride (floats)
#define BSTR 68                     // raw B row stride
#define A_FLOATS (BM * ASTR)        // 8704
#define B_FLOATS (EMBED * BSTR)     // 4352

__device__ __forceinline__ uint32_t f2tf32(float x) {
    uint32_t r;
    asm("cvt.rna.tf32.f32 %0, %1;" : "=r"(r) : "f"(x));
    return r;
}

__device__ __forceinline__ void mma_tf32(float* d, uint32_t a0, uint32_t a1,
                                         uint32_t a2, uint32_t a3,
                                         uint32_t b0, uint32_t b1) {
    asm("mma.sync.aligned.m16n8k8.row.col.f32.tf32.tf32.f32 "
        "{%0,%1,%2,%3}, {%4,%5,%6,%7}, {%8,%9}, {%0,%1,%2,%3};"
        : "+f"(d[0]), "+f"(d[1]), "+f"(d[2]), "+f"(d[3])
        : "r"(a0), "r"(a1), "r"(a2), "r"(a3), "r"(b0), "r"(b1));
}

// N-dim permutation: GEMM col n holds physical i = phi(n),
//   phi(16k + 8h + 2m + u) = 16k + 4m + 2h + u.
// Staging stores physical row i at smem row rho(i) = phi^{-1}(i):
//   i = 16k + 4m + 2h + u  ->  rho = 16k + 8h + 2m + u.
__device__ __forceinline__ int rho_row(int i) {
    return (i & 48) | (((i >> 1) & 1) << 3) | (((i >> 2) & 3) << 1) | (i & 1);
}

// Dense stage of K_p (64x64) -> raw smem [rho(i)*BSTR + j], tf32-rounded.
__device__ __forceinline__ void stage_B_raw(uint32_t* __restrict__ sB,
                                            const float* __restrict__ Kb, int t) {
    #pragma unroll
    for (int it = 0; it < 4; ++it) {
        int idx = it * NTHREADS + t;       // 0..1023 float4 slots
        int i   = idx >> 4;                // physical K row 0..63
        int j4  = idx & 15;
        float4 v = *(const float4*)(Kb + (size_t)i * KER_ROW + j4 * 4);
        uint4 w = { f2tf32(v.x), f2tf32(v.y), f2tf32(v.z), f2tf32(v.w) };
        *(uint4*)(sB + rho_row(i) * BSTR + j4 * 4) = w;
    }
}

__global__ void __launch_bounds__(NTHREADS, 2)
opn_mma_kernel(const float* __restrict__ emb, const float* __restrict__ ker,
               float* __restrict__ out)
{
    // smem (floats): sA raw 8704 | sB 4 x 4352 | sOut 1024
    extern __shared__ __align__(16) uint32_t dynsmem[];
    uint32_t* sA   = dynsmem;
    uint32_t* sB   = dynsmem + A_FLOATS;
    float*    sOut = (float*)(sB + 4 * B_FLOATS);

    const int t    = threadIdx.x;
    const int w    = t >> 5;
    const int lane = t & 31;
    const int wp   = w & 1;     // pair within group
    const int ws   = w >> 1;    // batch strip: rows [ws*32, ws*32+32)
    const int m    = lane & 3;
    const int batch_base = blockIdx.x * BM;

    // ---- decode chunk id -> (r, first pair p0, #pairs np, first col c0) ----
    int cid = blockIdx.y, r = 0, pbase = 0;
    while (true) {
        int cnt = 31 - r;
        int nch = (cnt + PCHUNK - 1) >> 3;
        if (cid < nch) break;
        cid -= nch; pbase += cnt; ++r;
    }
    const int p0 = pbase + cid * PCHUNK;
    const int np = min(PCHUNK, (31 - r) - cid * PCHUNK);
    const int c0 = r + 1 + cid * PCHUNK;

    // ---- stage A raw: sA[b*ASTR + j] = tf32(emb[batch_base+b, r, j]) ----
    {
        const float* Pb = emb + (size_t)batch_base * EMB_ROW + (size_t)r * EMBED;
        #pragma unroll
        for (int it = 0; it < 8; ++it) {
            int idx = it * NTHREADS + t;   // 0..2047 float4 slots
            int b   = idx >> 4;            // 0..127
            int j4  = idx & 15;
            float4 v = *(const float4*)(Pb + (size_t)b * EMB_ROW + j4 * 4);
            uint4 w_ = { f2tf32(v.x), f2tf32(v.y), f2tf32(v.z), f2tf32(v.w) };
            *(uint4*)(sA + b * ASTR + j4 * 4) = w_;
        }
    }
    stage_B_raw(sB, ker + (size_t)p0 * EMBED, t);
    if (np > 1) stage_B_raw(sB + B_FLOATS, ker + (size_t)(p0 + 1) * EMBED, t);
    __syncthreads();

    const int aBase = (ws * 32 + (lane >> 2)) * ASTR + m;
    const int bBase = (lane >> 2) * BSTR + m;

    const int ng = (np + 1) >> 1;
    for (int g = 0; g < ng; ++g) {
        const int cur = (g & 1) * 2;
        const int nxt = cur ^ 2;

        if (g + 1 < ng) {
            int pi = 2 * (g + 1);
            stage_B_raw(sB + nxt * B_FLOATS, ker + (size_t)(p0 + pi) * EMBED, t);
            if (pi + 1 < np)
                stage_B_raw(sB + (nxt + 1) * B_FLOATS, ker + (size_t)(p0 + pi + 1) * EMBED, t);
        }

        const int j = 2 * g + wp;          // pair slot within chunk
        if (j < np) {
            const uint32_t* Bp = sB + (cur + wp) * B_FLOATS + bBase;
            const uint32_t* Ap = sA + aBase;

            float acc[2][8][4];
            #pragma unroll
            for (int mm = 0; mm < 2; ++mm)
                #pragma unroll
                for (int nt = 0; nt < 8; ++nt)
                    #pragma unroll
                    for (int u = 0; u < 4; ++u)
                        acc[mm][nt][u] = 0.f;

            #pragma unroll
            for (int kt = 0; kt < 8; ++kt) {
                uint32_t a[2][4];
                #pragma unroll
                for (int mm = 0; mm < 2; ++mm) {
                    const uint32_t* Am = Ap + mm * 16 * ASTR + kt * 8;
                    a[mm][0] = Am[0];
                    a[mm][1] = Am[8 * ASTR];
                    a[mm][2] = Am[4];
                    a[mm][3] = Am[8 * ASTR + 4];
                }
                uint32_t b0[8], b1[8];
                #pragma unroll
                for (int nt = 0; nt < 8; ++nt) {
                    const uint32_t* Bn = Bp + nt * 8 * BSTR + kt * 8;
                    b0[nt] = Bn[0];
                    b1[nt] = Bn[4];
                }
                #pragma unroll
                for (int mm = 0; mm < 2; ++mm)
                    #pragma unroll
                    for (int nt = 0; nt < 8; ++nt)
                        mma_tf32(acc[mm][nt], a[mm][0], a[mm][1], a[mm][2], a[mm][3],
                                 b0[nt], b1[nt]);
            }

            // ---- epilogue: dense float4 q loads via the N permutation ----
            // acc[mm][2k+h][2v+u] pairs with q[row_v][16k + 4m + 2h + u]
            const int c = c0 + j;
            #pragma unroll
            for (int mm = 0; mm < 2; ++mm) {
                const int row0 = ws * 32 + mm * 16 + (lane >> 2);
                const float* q0 = emb + (size_t)(batch_base + row0) * EMB_ROW + (size_t)c * EMBED;
                const float* q1 = q0 + 8 * EMB_ROW;

                float s0 = 0.f, s1 = 0.f;
                #pragma unroll
                for (int k = 0; k < 4; ++k) {
                    float4 qv0 = *(const float4*)(q0 + k * 16 + m * 4);
                    float4 qv1 = *(const float4*)(q1 + k * 16 + m * 4);
                    s0 += qv0.x * acc[mm][2 * k][0] + qv0.y * acc[mm][2 * k][1]
                        + qv0.z * acc[mm][2 * k + 1][0] + qv0.w * acc[mm][2 * k + 1][1];
                    s1 += qv1.x * acc[mm][2 * k][2] + qv1.y * acc[mm][2 * k][3]
                        + qv1.z * acc[mm][2 * k + 1][2] + qv1.w * acc[mm][2 * k + 1][3];
                }
                s0 += __shfl_xor_sync(0xffffffffu, s0, 1);
                s0 += __shfl_xor_sync(0xffffffffu, s0, 2);
                s1 += __shfl_xor_sync(0xffffffffu, s1, 1);
                s1 += __shfl_xor_sync(0xffffffffu, s1, 2);

                if (m == 0) {
                    sOut[row0 * PCHUNK + j]       = s0;
                    sOut[(row0 + 8) * PCHUNK + j] = s1;
                }
            }
        }
        __syncthreads();   // B double-buffer + sOut ordering
    }

    // ---- coalesced output sweep ----
    #pragma unroll
    for (int u = 0; u < 4; ++u) {
        int idx = t * 4 + u;               // 0..1023
        int b = idx >> 3;
        int jj = idx & 7;
        if (jj < np)
            out[(size_t)(batch_base + b) * NPAIRS + p0 + jj] = sOut[idx];
    }
}

#define SMEM_TOTAL ((A_FLOATS + 4 * B_FLOATS + BM * PCHUNK) * 4)   // 108.5 KB

extern "C" void kernel_launch(void* const* d_in, const int* in_sizes, int n_in,
                              void* d_out, int out_size) {
    const float* emb = (const float*)d_in[0];   // (2048, 32, 64) f32
    const float* ker = (const float*)d_in[1];   // (64, 496, 64) f32
    float* out = (float*)d_out;                 // (2048, 1, 496) f32
    (void)in_sizes; (void)n_in; (void)out_size;

    static bool attr_set = false;
    if (!attr_set) {
        cudaFuncSetAttribute(opn_mma_kernel,
                             cudaFuncAttributeMaxDynamicSharedMemorySize, SMEM_TOTAL);
        attr_set = true;
    }
    dim3 grid(BATCH / BM, NCHUNKS);
    opn_mma_kernel<<<grid, NTHREADS, SMEM_TOTAL>>>(emb, ker, out);
}